// round 15
// baseline (speedup 1.0000x reference)
#include <cuda_runtime.h>
#include <cuda_bf16.h>
#include <cstdint>

#define NN 50000
#define EE 800000

// ---------------- device scratch ----------------
__device__ int   g_idx64;
__device__ int   g_counts[NN];
__device__ int   g_cursor[NN];
__device__ int   g_offsets[NN + 1];
__device__ float g_invdeg[NN];
__device__ int   g_ssrc[EE];
__device__ int   g_part[64];
__device__ float g_mean64[(size_t)NN * 64];
__device__ float g_z[(size_t)NN * 256];
__device__ float g_h1[(size_t)NN * 256];
__device__ float g_h2[(size_t)NN * 128];
__device__ float g_h3[(size_t)NN * 128];
__device__ float g_Wc[128 * 8];
__device__ float g_bc[8];

__device__ __forceinline__ const float* sel_buf(int sel, const float* x) {
    if (sel == 0) return x;
    if (sel == 1) return g_h1;
    if (sel == 2) return g_h2;
    if (sel == 3) return g_h3;
    if (sel == 4) return g_z;
    return g_mean64;
}
__device__ __forceinline__ float* sel_out(int sel) {
    if (sel == 1) return g_h1;
    if (sel == 2) return g_h2;
    if (sel == 3) return g_h3;
    return g_z;
}

// ---------------- dtype probe ----------------
__global__ void probe_kernel(const int* __restrict__ ei) {
    if (threadIdx.x == 0) {
        int orv = 0;
        #pragma unroll 1
        for (int i = 1; i < 256; i += 2) orv |= ei[i];
        g_idx64 = (orv == 0) ? 1 : 0;
    }
}
__device__ __forceinline__ int src_idx(const int* ei, int i) {
    return g_idx64 ? ei[2 * i] : ei[i];
}
__device__ __forceinline__ int tgt_idx(const int* ei, int i, int E) {
    return g_idx64 ? ei[2 * E + 2 * i] : ei[E + i];
}

// ---------------- CSR construction ----------------
__global__ void zero_counts_kernel(int n) {
    int i = blockIdx.x * blockDim.x + threadIdx.x;
    if (i < n) { g_counts[i] = 0; g_cursor[i] = 0; }
}
__global__ void hist_kernel(const int* __restrict__ ei, int E) {
    int i = blockIdx.x * blockDim.x + threadIdx.x;
    if (i < E) {
        int t = tgt_idx(ei, i, E);
        if ((unsigned)t < (unsigned)NN) atomicAdd(&g_counts[t], 1);
    }
}
__global__ void scan_block_kernel(int n) {
    __shared__ int warpsums[32];
    int b = blockIdx.x, tid = threadIdx.x;
    int i = b * 1024 + tid;
    int v = (i < n) ? g_counts[i] : 0;
    int lane = tid & 31, wid = tid >> 5;
    int s = v;
    #pragma unroll
    for (int d = 1; d < 32; d <<= 1) {
        int t = __shfl_up_sync(0xFFFFFFFFu, s, d);
        if (lane >= d) s += t;
    }
    if (lane == 31) warpsums[wid] = s;
    __syncthreads();
    if (wid == 0) {
        int ws = warpsums[lane];
        #pragma unroll
        for (int d = 1; d < 32; d <<= 1) {
            int t = __shfl_up_sync(0xFFFFFFFFu, ws, d);
            if (lane >= d) ws += t;
        }
        warpsums[lane] = ws;
    }
    __syncthreads();
    int incl = s + (wid > 0 ? warpsums[wid - 1] : 0);
    if (i < n) {
        g_offsets[i + 1] = incl;
        g_invdeg[i] = 1.0f / fmaxf((float)v, 1.0f);
    }
    if (tid == 1023) g_part[b] = incl;
}
__global__ void scan_part_kernel(int nb) {
    __shared__ int w0tot;
    int tid = threadIdx.x;
    int v = (tid < nb) ? g_part[tid] : 0;
    int lane = tid & 31;
    int s = v;
    #pragma unroll
    for (int d = 1; d < 32; d <<= 1) {
        int t = __shfl_up_sync(0xFFFFFFFFu, s, d);
        if (lane >= d) s += t;
    }
    if (tid == 31) w0tot = s;
    __syncthreads();
    if (tid >= 32) s += w0tot;
    if (tid < nb) g_part[tid] = s - v;
}
__global__ void scan_add_kernel(int n) {
    int b = blockIdx.x;
    int i = b * 1024 + threadIdx.x;
    if (i < n) g_offsets[i + 1] += g_part[b];
    if (i == 0) g_offsets[0] = 0;
}
__global__ void scatter_kernel(const int* __restrict__ ei, int E) {
    int i = blockIdx.x * blockDim.x + threadIdx.x;
    if (i < E) {
        int t = tgt_idx(ei, i, E);
        int s = src_idx(ei, i);
        if ((unsigned)t < (unsigned)NN && (unsigned)s < (unsigned)NN) {
            int pos = g_offsets[t] + atomicAdd(&g_cursor[t], 1);
            g_ssrc[pos] = s;
        }
    }
}

// ---------------- aggregations (simple loop — ptxas schedules best) ----
__global__ void aggregate64_kernel(const float* __restrict__ X, int N) {
    int node = (blockIdx.x * blockDim.x + threadIdx.x) >> 5;
    int lane = threadIdx.x & 31;
    if (node >= N) return;
    int s = g_offsets[node], e = g_offsets[node + 1];
    float acc0 = 0.f, acc1 = 0.f;
    for (int i = s; i < e; i++) {
        int srow = g_ssrc[i];
        float2 v = *(const float2*)(X + (size_t)srow * 64 + lane * 2);
        acc0 += v.x; acc1 += v.y;
    }
    float inv = g_invdeg[node];
    float2 r; r.x = acc0 * inv; r.y = acc1 * inv;
    *(float2*)(g_mean64 + (size_t)node * 64 + lane * 2) = r;
}

__global__ void agg_combine_kernel(int selOut, const float* __restrict__ bias, int N) {
    const float* __restrict__ Z = g_z;
    float* __restrict__ O = sel_out(selOut);
    int node = (blockIdx.x * blockDim.x + threadIdx.x) >> 5;
    int lane = threadIdx.x & 31;
    if (node >= N) return;
    int s = g_offsets[node], e = g_offsets[node + 1];
    float a0 = 0.f, a1 = 0.f, a2 = 0.f, a3 = 0.f;
    for (int i = s; i < e; i++) {
        int srow = g_ssrc[i];
        float4 v = *(const float4*)(Z + (size_t)srow * 256 + lane * 4);
        a0 += v.x; a1 += v.y; a2 += v.z; a3 += v.w;
    }
    float inv = g_invdeg[node];
    float4 zr = *(const float4*)(Z + (size_t)node * 256 + 128 + lane * 4);
    float4 bv = *(const float4*)(bias + lane * 4);
    float4 r;
    r.x = fmaxf(a0 * inv + bv.x + zr.x, 0.f);
    r.y = fmaxf(a1 * inv + bv.y + zr.y, 0.f);
    r.z = fmaxf(a2 * inv + bv.z + zr.z, 0.f);
    r.w = fmaxf(a3 * inv + bv.w + zr.w, 0.f);
    *(float4*)(O + (size_t)node * 128 + lane * 4) = r;
}

// layer-3 only: gather + combine + folded head -> out (8 floats/node)
__global__ void agg_head_kernel(const float* __restrict__ bias,
                                float* __restrict__ out, int N) {
    const float* __restrict__ Z = g_z;
    int node = (blockIdx.x * blockDim.x + threadIdx.x) >> 5;
    int lane = threadIdx.x & 31;
    if (node >= N) return;
    int s = g_offsets[node], e = g_offsets[node + 1];
    float a0 = 0.f, a1 = 0.f, a2 = 0.f, a3 = 0.f;
    for (int i = s; i < e; i++) {
        int srow = g_ssrc[i];
        float4 v = *(const float4*)(Z + (size_t)srow * 256 + lane * 4);
        a0 += v.x; a1 += v.y; a2 += v.z; a3 += v.w;
    }
    float inv = g_invdeg[node];
    float4 zr = *(const float4*)(Z + (size_t)node * 256 + 128 + lane * 4);
    float4 bv = *(const float4*)(bias + lane * 4);
    float hx = fmaxf(a0 * inv + bv.x + zr.x, 0.f);
    float hy = fmaxf(a1 * inv + bv.y + zr.y, 0.f);
    float hz = fmaxf(a2 * inv + bv.z + zr.z, 0.f);
    float hw = fmaxf(a3 * inv + bv.w + zr.w, 0.f);
    float p[8];
    const float* Wrow = g_Wc + lane * 32;
    #pragma unroll
    for (int j = 0; j < 8; j++)
        p[j] = hx * Wrow[j] + hy * Wrow[8 + j] + hz * Wrow[16 + j] + hw * Wrow[24 + j];
    #pragma unroll
    for (int d = 16; d >= 1; d >>= 1) {
        #pragma unroll
        for (int j = 0; j < 8; j++)
            p[j] += __shfl_xor_sync(0xFFFFFFFFu, p[j], d);
    }
    if (lane < 8) out[(size_t)node * 8 + lane] = p[lane] + g_bc[lane];
}

// ---------------- GEMM: double-buffered, packed f32x2 FMA ----------------
#define GBM 128
#define GBN 128
#define GBK 16
#define APAD 4

__global__ __launch_bounds__(256, 2)
void sage_gemm_kernel(int mode, int selAa, int selAb, const float* __restrict__ x,
                      int selC, int K1, int Ktot,
                      const float* __restrict__ Bl,
                      const float* __restrict__ Br,
                      const float* __restrict__ bias,  // nullptr = no bias/relu
                      int N) {
    const float* __restrict__ Aa = sel_buf(selAa, x);
    const float* __restrict__ Ab = sel_buf(selAb, x);
    float* __restrict__ C = sel_out(selC);
    const int M = 256;

    __shared__ float As[2][GBK][GBM + APAD];
    __shared__ float Bs[2][GBK][GBN];

    int block_row = blockIdx.y * GBM;
    int block_col = blockIdx.x * GBN;
    int tid = threadIdx.x;
    int tr = tid >> 4;
    int tc = tid & 15;

    int arow = tid >> 2;
    int ac4  = (tid & 3) * 4;
    int brow = tid >> 5;
    int bc4  = (tid & 31) * 4;

    float4 aR[2], bR[2];

    auto load_tiles = [&](int k0) {
        #pragma unroll
        for (int l = 0; l < 2; l++) {
            int row = arow + l * 64;
            int grow = block_row + row;
            int gk = k0 + ac4;
            float4 v = make_float4(0.f, 0.f, 0.f, 0.f);
            if (grow < N) {
                if (gk < K1) v = *(const float4*)(Aa + (size_t)grow * K1 + gk);
                else         v = *(const float4*)(Ab + (size_t)grow * K1 + (gk - K1));
            }
            aR[l] = v;
        }
        #pragma unroll
        for (int l = 0; l < 2; l++) {
            int gk = k0 + brow + l * 8;
            const float* p;
            if (mode == 0) {
                p = (gk < K1) ? (Bl + (size_t)gk * M + block_col + bc4)
                              : (Br + (size_t)(gk - K1) * M + block_col + bc4);
            } else {
                const float* W = (block_col < 128) ? Bl : Br;
                p = W + (size_t)gk * 128 + (block_col & 127) + bc4;
            }
            bR[l] = *(const float4*)p;
        }
    };
    auto store_tiles = [&](int buf) {
        #pragma unroll
        for (int l = 0; l < 2; l++) {
            int row = arow + l * 64;
            As[buf][ac4 + 0][row] = aR[l].x;
            As[buf][ac4 + 1][row] = aR[l].y;
            As[buf][ac4 + 2][row] = aR[l].z;
            As[buf][ac4 + 3][row] = aR[l].w;
        }
        #pragma unroll
        for (int l = 0; l < 2; l++)
            *(float4*)(&Bs[buf][brow + l * 8][bc4]) = bR[l];
    };

    unsigned long long acc2[8][4];
    #pragma unroll
    for (int i = 0; i < 8; i++)
        #pragma unroll
        for (int j = 0; j < 4; j++) acc2[i][j] = 0ULL;

    const int nt = Ktot / GBK;
    load_tiles(0);
    store_tiles(0);
    __syncthreads();

    for (int t = 0; t < nt; t++) {
        int cur = t & 1;
        if (t + 1 < nt) load_tiles((t + 1) * GBK);
        #pragma unroll
        for (int kk = 0; kk < GBK; kk++) {
            float a[8];
            *(float4*)(a)     = *(const float4*)(&As[cur][kk][tr * 8]);
            *(float4*)(a + 4) = *(const float4*)(&As[cur][kk][tr * 8 + 4]);
            ulonglong2 bA = *(const ulonglong2*)(&Bs[cur][kk][tc * 8]);
            ulonglong2 bB = *(const ulonglong2*)(&Bs[cur][kk][tc * 8 + 4]);
            unsigned long long bp0 = bA.x, bp1 = bA.y, bp2 = bB.x, bp3 = bB.y;
            #pragma unroll
            for (int i = 0; i < 8; i++) {
                unsigned long long aa;
                asm("mov.b64 %0, {%1, %1};" : "=l"(aa) : "r"(__float_as_uint(a[i])));
                asm("fma.rn.f32x2 %0, %1, %2, %0;" : "+l"(acc2[i][0]) : "l"(aa), "l"(bp0));
                asm("fma.rn.f32x2 %0, %1, %2, %0;" : "+l"(acc2[i][1]) : "l"(aa), "l"(bp1));
                asm("fma.rn.f32x2 %0, %1, %2, %0;" : "+l"(acc2[i][2]) : "l"(aa), "l"(bp2));
                asm("fma.rn.f32x2 %0, %1, %2, %0;" : "+l"(acc2[i][3]) : "l"(aa), "l"(bp3));
            }
        }
        if (t + 1 < nt) {
            store_tiles(cur ^ 1);
            __syncthreads();
        }
    }

    const bool hasBias = (bias != nullptr);
    #pragma unroll
    for (int i = 0; i < 8; i++) {
        int grow = block_row + tr * 8 + i;
        if (grow >= N) continue;
        #pragma unroll
        for (int j = 0; j < 2; j++) {
            int gcol = block_col + tc * 8 + j * 4;
            float4 r;
            {
                uint32_t lo, hi;
                asm("mov.b64 {%0, %1}, %2;" : "=r"(lo), "=r"(hi) : "l"(acc2[i][j * 2]));
                r.x = __uint_as_float(lo); r.y = __uint_as_float(hi);
                asm("mov.b64 {%0, %1}, %2;" : "=r"(lo), "=r"(hi) : "l"(acc2[i][j * 2 + 1]));
                r.z = __uint_as_float(lo); r.w = __uint_as_float(hi);
            }
            if (hasBias) {
                r.x = fmaxf(r.x + bias[gcol + 0], 0.f);
                r.y = fmaxf(r.y + bias[gcol + 1], 0.f);
                r.z = fmaxf(r.z + bias[gcol + 2], 0.f);
                r.w = fmaxf(r.w + bias[gcol + 3], 0.f);
            }
            *(float4*)(C + (size_t)grow * 256 + gcol) = r;
        }
    }
}

// ---------------- head ----------------
__global__ void combine_head_kernel(const float* __restrict__ Wlin,
                                    const float* __restrict__ blin,
                                    const float* __restrict__ Wlin2,
                                    const float* __restrict__ blin2) {
    int tid = threadIdx.x;
    int k = tid >> 3, j = tid & 7;
    float s = 0.f;
    #pragma unroll 8
    for (int l = 0; l < 128; l++) s += Wlin[k * 128 + l] * Wlin2[l * 8 + j];
    g_Wc[k * 8 + j] = s;
    if (k == 0) {
        float t = 0.f;
        for (int l = 0; l < 128; l++) t += blin[l] * Wlin2[l * 8 + j];
        g_bc[j] = t + blin2[j];
    }
}

__global__ void head_kernel(float* __restrict__ out, int N) {
    const float* __restrict__ h3 = g_h3;
    __shared__ float sW[128 * 8];
    __shared__ float sb[8];
    __shared__ float sh[32][132];

    for (int i = threadIdx.x; i < 1024; i += 256) sW[i] = g_Wc[i];
    if (threadIdx.x < 8) sb[threadIdx.x] = g_bc[threadIdx.x];

    int row0 = blockIdx.x * 32;
    for (int l = threadIdx.x; l < 1024; l += 256) {
        int r = l >> 5;
        int c4 = (l & 31) * 4;
        int grow = row0 + r;
        float4 v = (grow < N) ? *(const float4*)(h3 + (size_t)grow * 128 + c4)
                              : make_float4(0.f, 0.f, 0.f, 0.f);
        *(float4*)(&sh[r][c4]) = v;
    }
    __syncthreads();

    int r = threadIdx.x >> 3;
    int j = threadIdx.x & 7;
    float s = sb[j];
    #pragma unroll 8
    for (int k = 0; k < 128; k++) s += sh[r][k] * sW[k * 8 + j];
    int grow = row0 + r;
    if (grow < N) out[(size_t)grow * 8 + j] = s;
}

// ---------------- launch ----------------
extern "C" void kernel_launch(void* const* d_in, const int* in_sizes, int n_in,
                              void* d_out, int out_size) {
    const float* x    = (const float*)d_in[0];
    const int*   ei   = (const int*)d_in[1];
    const float* Wf_l = (const float*)d_in[2];
    const float* bf   = (const float*)d_in[3];
    const float* Wf_r = (const float*)d_in[4];
    const float* W0_l = (const float*)d_in[5];
    const float* b0   = (const float*)d_in[6];
    const float* W0_r = (const float*)d_in[7];
    const float* W1_l = (const float*)d_in[8];
    const float* b1   = (const float*)d_in[9];
    const float* W1_r = (const float*)d_in[10];
    const float* W_lin  = (const float*)d_in[11];
    const float* b_lin  = (const float*)d_in[12];
    const float* W_lin2 = (const float*)d_in[13];
    const float* b_lin2 = (const float*)d_in[14];
    float* out = (float*)d_out;

    const int N = NN;
    const int E = in_sizes[1] / 2;
    const int scanBlocks = (N + 1023) / 1024;

    // CSR build (identical to R14)
    probe_kernel<<<1, 32>>>(ei);
    zero_counts_kernel<<<(N + 255) / 256, 256>>>(N);
    hist_kernel<<<(E + 255) / 256, 256>>>(ei, E);
    scan_block_kernel<<<scanBlocks, 1024>>>(N);
    scan_part_kernel<<<1, 64>>>(scanBlocks);
    scan_add_kernel<<<scanBlocks, 1024>>>(N);
    scatter_kernel<<<(E + 255) / 256, 256>>>(ei, E);

    const int aggBlocks = (N * 32 + 255) / 256;
    const int rowTiles = (N + GBM - 1) / GBM;
    dim3 gemmGrid(2, rowTiles);

    // head weight fold (depends only on weights; must precede agg_head)
    combine_head_kernel<<<1, 1024>>>(W_lin, b_lin, W_lin2, b_lin2);

    // Layer 1: h1 = relu([mean64(x) | x] @ [Wf_l;Wf_r] + bf)
    aggregate64_kernel<<<aggBlocks, 256>>>(x, N);
    sage_gemm_kernel<<<gemmGrid, 256>>>(0, 5, 0, x, 1, 64, 128,
                                        Wf_l, Wf_r, bf, N);

    // Layer 2: z = h1 @ [W0_l || W0_r]; h2 = relu(mean(z_l) + b0 + z_r)
    sage_gemm_kernel<<<gemmGrid, 256>>>(1, 1, 1, x, 4, 256, 256,
                                        W0_l, W0_r, nullptr, N);
    agg_combine_kernel<<<aggBlocks, 256>>>(2, b0, N);

    // Layer 3: z = h2 @ [W1_l || W1_r]; fused gather+combine+head -> out
    sage_gemm_kernel<<<gemmGrid, 256>>>(1, 2, 2, x, 4, 128, 128,
                                        W1_l, W1_r, nullptr, N);
    agg_head_kernel<<<aggBlocks, 256>>>(b1, out, N);
}

// round 16
// speedup vs baseline: 1.3970x; 1.3970x over previous
#include <cuda_runtime.h>
#include <cuda_bf16.h>
#include <cuda_fp16.h>
#include <cstdint>

#define NN 50000
#define EE 800000

// ---------------- device scratch ----------------
__device__ int   g_idx64;
__device__ int   g_counts[NN];
__device__ int   g_cursor[NN];
__device__ int   g_offsets[NN + 1];
__device__ float g_invdeg[NN];
__device__ int   g_ssrc[EE];
__device__ int   g_part[64];
__device__ float g_mean64[(size_t)NN * 64];
__device__ float g_z[(size_t)NN * 256];        // mode1: z_r fp32 lives in first N*128
__device__ __half g_zl[(size_t)NN * 128];      // mode1: z_l fp16 (gathered operand)
__device__ float g_h1[(size_t)NN * 256];
__device__ float g_h2[(size_t)NN * 128];
__device__ float g_h3[(size_t)NN * 128];
__device__ float g_Wc[128 * 8];
__device__ float g_bc[8];

__device__ __forceinline__ const float* sel_buf(int sel, const float* x) {
    if (sel == 0) return x;
    if (sel == 1) return g_h1;
    if (sel == 2) return g_h2;
    if (sel == 3) return g_h3;
    if (sel == 4) return g_z;
    return g_mean64;
}
__device__ __forceinline__ float* sel_out(int sel) {
    if (sel == 1) return g_h1;
    if (sel == 2) return g_h2;
    if (sel == 3) return g_h3;
    return g_z;
}

// ---------------- dtype probe ----------------
__global__ void probe_kernel(const int* __restrict__ ei) {
    if (threadIdx.x == 0) {
        int orv = 0;
        #pragma unroll 1
        for (int i = 1; i < 256; i += 2) orv |= ei[i];
        g_idx64 = (orv == 0) ? 1 : 0;
    }
}
__device__ __forceinline__ int src_idx(const int* ei, int i) {
    return g_idx64 ? ei[2 * i] : ei[i];
}
__device__ __forceinline__ int tgt_idx(const int* ei, int i, int E) {
    return g_idx64 ? ei[2 * E + 2 * i] : ei[E + i];
}

// ---------------- CSR construction ----------------
__global__ void zero_counts_kernel(int n) {
    int i = blockIdx.x * blockDim.x + threadIdx.x;
    if (i < n) { g_counts[i] = 0; g_cursor[i] = 0; }
}
__global__ void hist_kernel(const int* __restrict__ ei, int E) {
    int i = blockIdx.x * blockDim.x + threadIdx.x;
    if (i < E) {
        int t = tgt_idx(ei, i, E);
        if ((unsigned)t < (unsigned)NN) atomicAdd(&g_counts[t], 1);
    }
}
__global__ void scan_block_kernel(int n) {
    __shared__ int warpsums[32];
    int b = blockIdx.x, tid = threadIdx.x;
    int i = b * 1024 + tid;
    int v = (i < n) ? g_counts[i] : 0;
    int lane = tid & 31, wid = tid >> 5;
    int s = v;
    #pragma unroll
    for (int d = 1; d < 32; d <<= 1) {
        int t = __shfl_up_sync(0xFFFFFFFFu, s, d);
        if (lane >= d) s += t;
    }
    if (lane == 31) warpsums[wid] = s;
    __syncthreads();
    if (wid == 0) {
        int ws = warpsums[lane];
        #pragma unroll
        for (int d = 1; d < 32; d <<= 1) {
            int t = __shfl_up_sync(0xFFFFFFFFu, ws, d);
            if (lane >= d) ws += t;
        }
        warpsums[lane] = ws;
    }
    __syncthreads();
    int incl = s + (wid > 0 ? warpsums[wid - 1] : 0);
    if (i < n) {
        g_offsets[i + 1] = incl;
        g_invdeg[i] = 1.0f / fmaxf((float)v, 1.0f);
    }
    if (tid == 1023) g_part[b] = incl;
}
__global__ void scan_part_kernel(int nb) {
    __shared__ int w0tot;
    int tid = threadIdx.x;
    int v = (tid < nb) ? g_part[tid] : 0;
    int lane = tid & 31;
    int s = v;
    #pragma unroll
    for (int d = 1; d < 32; d <<= 1) {
        int t = __shfl_up_sync(0xFFFFFFFFu, s, d);
        if (lane >= d) s += t;
    }
    if (tid == 31) w0tot = s;
    __syncthreads();
    if (tid >= 32) s += w0tot;
    if (tid < nb) g_part[tid] = s - v;
}
__global__ void scan_add_kernel(int n) {
    int b = blockIdx.x;
    int i = b * 1024 + threadIdx.x;
    if (i < n) g_offsets[i + 1] += g_part[b];
    if (i == 0) g_offsets[0] = 0;
}
__global__ void scatter_kernel(const int* __restrict__ ei, int E) {
    int i = blockIdx.x * blockDim.x + threadIdx.x;
    if (i < E) {
        int t = tgt_idx(ei, i, E);
        int s = src_idx(ei, i);
        if ((unsigned)t < (unsigned)NN && (unsigned)s < (unsigned)NN) {
            int pos = g_offsets[t] + atomicAdd(&g_cursor[t], 1);
            g_ssrc[pos] = s;
        }
    }
}

// ---------------- aggregations ----------------
__global__ void aggregate64_kernel(const float* __restrict__ X, int N) {
    int node = (blockIdx.x * blockDim.x + threadIdx.x) >> 5;
    int lane = threadIdx.x & 31;
    if (node >= N) return;
    int s = g_offsets[node], e = g_offsets[node + 1];
    float acc0 = 0.f, acc1 = 0.f;
    for (int i = s; i < e; i++) {
        int srow = g_ssrc[i];
        float2 v = *(const float2*)(X + (size_t)srow * 64 + lane * 2);
        acc0 += v.x; acc1 += v.y;
    }
    float inv = g_invdeg[node];
    float2 r; r.x = acc0 * inv; r.y = acc1 * inv;
    *(float2*)(g_mean64 + (size_t)node * 64 + lane * 2) = r;
}

// layers 2/3: gather z_l (fp16), combine with z_r (fp32) + bias, relu
__global__ void agg_combine_kernel(int selOut, const float* __restrict__ bias, int N) {
    const __half* __restrict__ Zl = g_zl;
    const float* __restrict__ Zr = g_z;   // N x 128 fp32
    float* __restrict__ O = sel_out(selOut);
    int node = (blockIdx.x * blockDim.x + threadIdx.x) >> 5;
    int lane = threadIdx.x & 31;
    if (node >= N) return;
    int s = g_offsets[node], e = g_offsets[node + 1];
    float a0 = 0.f, a1 = 0.f, a2 = 0.f, a3 = 0.f;
    for (int i = s; i < e; i++) {
        int srow = g_ssrc[i];
        uint2 raw = *(const uint2*)(Zl + (size_t)srow * 128 + lane * 4);
        __half2 h01 = *(__half2*)&raw.x;
        __half2 h23 = *(__half2*)&raw.y;
        float2 f01 = __half22float2(h01);
        float2 f23 = __half22float2(h23);
        a0 += f01.x; a1 += f01.y; a2 += f23.x; a3 += f23.y;
    }
    float inv = g_invdeg[node];
    float4 zr = *(const float4*)(Zr + (size_t)node * 128 + lane * 4);
    float4 bv = *(const float4*)(bias + lane * 4);
    float4 r;
    r.x = fmaxf(a0 * inv + bv.x + zr.x, 0.f);
    r.y = fmaxf(a1 * inv + bv.y + zr.y, 0.f);
    r.z = fmaxf(a2 * inv + bv.z + zr.z, 0.f);
    r.w = fmaxf(a3 * inv + bv.w + zr.w, 0.f);
    *(float4*)(O + (size_t)node * 128 + lane * 4) = r;
}

// ---------------- GEMM: double-buffered, packed f32x2 FMA ----------------
#define GBM 128
#define GBN 128
#define GBK 16
#define APAD 4

__global__ __launch_bounds__(256, 2)
void sage_gemm_kernel(int mode, int selAa, int selAb, const float* __restrict__ x,
                      int selC, int K1, int Ktot,
                      const float* __restrict__ Bl,
                      const float* __restrict__ Br,
                      const float* __restrict__ bias,  // nullptr = no bias/relu
                      int N) {
    const float* __restrict__ Aa = sel_buf(selAa, x);
    const float* __restrict__ Ab = sel_buf(selAb, x);
    float* __restrict__ C = sel_out(selC);
    const int M = 256;

    __shared__ float As[2][GBK][GBM + APAD];
    __shared__ float Bs[2][GBK][GBN];

    int block_row = blockIdx.y * GBM;
    int block_col = blockIdx.x * GBN;
    int tid = threadIdx.x;
    int tr = tid >> 4;
    int tc = tid & 15;

    int arow = tid >> 2;
    int ac4  = (tid & 3) * 4;
    int brow = tid >> 5;
    int bc4  = (tid & 31) * 4;

    float4 aR[2], bR[2];

    auto load_tiles = [&](int k0) {
        #pragma unroll
        for (int l = 0; l < 2; l++) {
            int row = arow + l * 64;
            int grow = block_row + row;
            int gk = k0 + ac4;
            float4 v = make_float4(0.f, 0.f, 0.f, 0.f);
            if (grow < N) {
                if (gk < K1) v = *(const float4*)(Aa + (size_t)grow * K1 + gk);
                else         v = *(const float4*)(Ab + (size_t)grow * K1 + (gk - K1));
            }
            aR[l] = v;
        }
        #pragma unroll
        for (int l = 0; l < 2; l++) {
            int gk = k0 + brow + l * 8;
            const float* p;
            if (mode == 0) {
                p = (gk < K1) ? (Bl + (size_t)gk * M + block_col + bc4)
                              : (Br + (size_t)(gk - K1) * M + block_col + bc4);
            } else {
                const float* W = (block_col < 128) ? Bl : Br;
                p = W + (size_t)gk * 128 + (block_col & 127) + bc4;
            }
            bR[l] = *(const float4*)p;
        }
    };
    auto store_tiles = [&](int buf) {
        #pragma unroll
        for (int l = 0; l < 2; l++) {
            int row = arow + l * 64;
            As[buf][ac4 + 0][row] = aR[l].x;
            As[buf][ac4 + 1][row] = aR[l].y;
            As[buf][ac4 + 2][row] = aR[l].z;
            As[buf][ac4 + 3][row] = aR[l].w;
        }
        #pragma unroll
        for (int l = 0; l < 2; l++)
            *(float4*)(&Bs[buf][brow + l * 8][bc4]) = bR[l];
    };

    unsigned long long acc2[8][4];
    #pragma unroll
    for (int i = 0; i < 8; i++)
        #pragma unroll
        for (int j = 0; j < 4; j++) acc2[i][j] = 0ULL;

    const int nt = Ktot / GBK;
    load_tiles(0);
    store_tiles(0);
    __syncthreads();

    for (int t = 0; t < nt; t++) {
        int cur = t & 1;
        if (t + 1 < nt) load_tiles((t + 1) * GBK);
        #pragma unroll
        for (int kk = 0; kk < GBK; kk++) {
            float a[8];
            *(float4*)(a)     = *(const float4*)(&As[cur][kk][tr * 8]);
            *(float4*)(a + 4) = *(const float4*)(&As[cur][kk][tr * 8 + 4]);
            ulonglong2 bA = *(const ulonglong2*)(&Bs[cur][kk][tc * 8]);
            ulonglong2 bB = *(const ulonglong2*)(&Bs[cur][kk][tc * 8 + 4]);
            unsigned long long bp0 = bA.x, bp1 = bA.y, bp2 = bB.x, bp3 = bB.y;
            #pragma unroll
            for (int i = 0; i < 8; i++) {
                unsigned long long aa;
                asm("mov.b64 %0, {%1, %1};" : "=l"(aa) : "r"(__float_as_uint(a[i])));
                asm("fma.rn.f32x2 %0, %1, %2, %0;" : "+l"(acc2[i][0]) : "l"(aa), "l"(bp0));
                asm("fma.rn.f32x2 %0, %1, %2, %0;" : "+l"(acc2[i][1]) : "l"(aa), "l"(bp1));
                asm("fma.rn.f32x2 %0, %1, %2, %0;" : "+l"(acc2[i][2]) : "l"(aa), "l"(bp2));
                asm("fma.rn.f32x2 %0, %1, %2, %0;" : "+l"(acc2[i][3]) : "l"(aa), "l"(bp3));
            }
        }
        if (t + 1 < nt) {
            store_tiles(cur ^ 1);
            __syncthreads();
        }
    }

    const bool hasBias = (bias != nullptr);
    #pragma unroll
    for (int i = 0; i < 8; i++) {
        int grow = block_row + tr * 8 + i;
        if (grow >= N) continue;
        #pragma unroll
        for (int j = 0; j < 2; j++) {
            int gcol = block_col + tc * 8 + j * 4;
            float4 r;
            {
                uint32_t lo, hi;
                asm("mov.b64 {%0, %1}, %2;" : "=r"(lo), "=r"(hi) : "l"(acc2[i][j * 2]));
                r.x = __uint_as_float(lo); r.y = __uint_as_float(hi);
                asm("mov.b64 {%0, %1}, %2;" : "=r"(lo), "=r"(hi) : "l"(acc2[i][j * 2 + 1]));
                r.z = __uint_as_float(lo); r.w = __uint_as_float(hi);
            }
            if (mode == 1) {
                // left half -> fp16 z_l (gathered); right half -> fp32 z_r
                if (block_col < 128) {
                    __half2 h01 = __floats2half2_rn(r.x, r.y);
                    __half2 h23 = __floats2half2_rn(r.z, r.w);
                    uint2 raw;
                    raw.x = *(uint32_t*)&h01;
                    raw.y = *(uint32_t*)&h23;
                    *(uint2*)(g_zl + (size_t)grow * 128 + gcol) = raw;
                } else {
                    *(float4*)(g_z + (size_t)grow * 128 + (gcol - 128)) = r;
                }
            } else {
                if (hasBias) {
                    r.x = fmaxf(r.x + bias[gcol + 0], 0.f);
                    r.y = fmaxf(r.y + bias[gcol + 1], 0.f);
                    r.z = fmaxf(r.z + bias[gcol + 2], 0.f);
                    r.w = fmaxf(r.w + bias[gcol + 3], 0.f);
                }
                *(float4*)(C + (size_t)grow * 256 + gcol) = r;
            }
        }
    }
}

// ---------------- head ----------------
__global__ void combine_head_kernel(const float* __restrict__ Wlin,
                                    const float* __restrict__ blin,
                                    const float* __restrict__ Wlin2,
                                    const float* __restrict__ blin2) {
    int tid = threadIdx.x;
    int k = tid >> 3, j = tid & 7;
    float s = 0.f;
    #pragma unroll 8
    for (int l = 0; l < 128; l++) s += Wlin[k * 128 + l] * Wlin2[l * 8 + j];
    g_Wc[k * 8 + j] = s;
    if (k == 0) {
        float t = 0.f;
        for (int l = 0; l < 128; l++) t += blin[l] * Wlin2[l * 8 + j];
        g_bc[j] = t + blin2[j];
    }
}

__global__ void head_kernel(float* __restrict__ out, int N) {
    const float* __restrict__ h3 = g_h3;
    __shared__ float sW[128 * 8];
    __shared__ float sb[8];
    __shared__ float sh[32][132];

    for (int i = threadIdx.x; i < 1024; i += 256) sW[i] = g_Wc[i];
    if (threadIdx.x < 8) sb[threadIdx.x] = g_bc[threadIdx.x];

    int row0 = blockIdx.x * 32;
    for (int l = threadIdx.x; l < 1024; l += 256) {
        int r = l >> 5;
        int c4 = (l & 31) * 4;
        int grow = row0 + r;
        float4 v = (grow < N) ? *(const float4*)(h3 + (size_t)grow * 128 + c4)
                              : make_float4(0.f, 0.f, 0.f, 0.f);
        *(float4*)(&sh[r][c4]) = v;
    }
    __syncthreads();

    int r = threadIdx.x >> 3;
    int j = threadIdx.x & 7;
    float s = sb[j];
    #pragma unroll 8
    for (int k = 0; k < 128; k++) s += sh[r][k] * sW[k * 8 + j];
    int grow = row0 + r;
    if (grow < N) out[(size_t)grow * 8 + j] = s;
}

// ---------------- launch ----------------
extern "C" void kernel_launch(void* const* d_in, const int* in_sizes, int n_in,
                              void* d_out, int out_size) {
    const float* x    = (const float*)d_in[0];
    const int*   ei   = (const int*)d_in[1];
    const float* Wf_l = (const float*)d_in[2];
    const float* bf   = (const float*)d_in[3];
    const float* Wf_r = (const float*)d_in[4];
    const float* W0_l = (const float*)d_in[5];
    const float* b0   = (const float*)d_in[6];
    const float* W0_r = (const float*)d_in[7];
    const float* W1_l = (const float*)d_in[8];
    const float* b1   = (const float*)d_in[9];
    const float* W1_r = (const float*)d_in[10];
    const float* W_lin  = (const float*)d_in[11];
    const float* b_lin  = (const float*)d_in[12];
    const float* W_lin2 = (const float*)d_in[13];
    const float* b_lin2 = (const float*)d_in[14];
    float* out = (float*)d_out;

    const int N = NN;
    const int E = in_sizes[1] / 2;
    const int scanBlocks = (N + 1023) / 1024;

    // CSR build
    probe_kernel<<<1, 32>>>(ei);
    zero_counts_kernel<<<(N + 255) / 256, 256>>>(N);
    hist_kernel<<<(E + 255) / 256, 256>>>(ei, E);
    scan_block_kernel<<<scanBlocks, 1024>>>(N);
    scan_part_kernel<<<1, 64>>>(scanBlocks);
    scan_add_kernel<<<scanBlocks, 1024>>>(N);
    scatter_kernel<<<(E + 255) / 256, 256>>>(ei, E);

    const int aggBlocks = (N * 32 + 255) / 256;
    const int rowTiles = (N + GBM - 1) / GBM;
    dim3 gemmGrid(2, rowTiles);

    // Layer 1: h1 = relu([mean64(x) | x] @ [Wf_l;Wf_r] + bf)
    aggregate64_kernel<<<aggBlocks, 256>>>(x, N);
    sage_gemm_kernel<<<gemmGrid, 256>>>(0, 5, 0, x, 1, 64, 128,
                                        Wf_l, Wf_r, bf, N);

    // Layer 2: z_l(fp16)/z_r(fp32) = h1 @ [W0_l || W0_r]; h2 = relu(mean+b0+z_r)
    sage_gemm_kernel<<<gemmGrid, 256>>>(1, 1, 1, x, 4, 256, 256,
                                        W0_l, W0_r, nullptr, N);
    agg_combine_kernel<<<aggBlocks, 256>>>(2, b0, N);

    // Layer 3: z_l/z_r = h2 @ [W1_l || W1_r]; h3 = relu(mean+b1+z_r)
    sage_gemm_kernel<<<gemmGrid, 256>>>(1, 2, 2, x, 4, 128, 128,
                                        W1_l, W1_r, nullptr, N);
    agg_combine_kernel<<<aggBlocks, 256>>>(3, b1, N);

    // Head
    combine_head_kernel<<<1, 1024>>>(W_lin, b_lin, W_lin2, b_lin2);
    head_kernel<<<(N + 31) / 32, 256>>>(out, N);
}